// round 5
// baseline (speedup 1.0000x reference)
#include <cuda_runtime.h>
#include <math.h>

#define BB 8
#define SS 512
#define DD 128
#define HH 512
#define NB 32
#define NH 5
#define OO 6
#define RR (BB*SS)   // 4096 token rows

// -------- scratch (static device globals; no allocation at runtime) --------
__device__ float g_x[RR*DD];        // activations [B,S,D]
__device__ float g_q[RR*DD];
__device__ float g_v[RR*DD];
__device__ float g_E[BB*SS*SS];     // G, then E, then combined weights Wc (in place)
__device__ float g_h[RR*HH];        // FFN hidden
__device__ float g_acc[RR*DD];      // attention out / FFN out
__device__ int   g_bucket[RR];
__device__ int   g_cnt[BB*NB];
__device__ float g_vb[BB*NB*DD];    // per-bucket v sums

__device__ __forceinline__ float warpSum(float v){
  #pragma unroll
  for (int o=16;o;o>>=1) v += __shfl_xor_sync(0xffffffffu, v, o);
  return v;
}
__device__ __forceinline__ float warpMax(float v){
  #pragma unroll
  for (int o=16;o;o>>=1) v = fmaxf(v, __shfl_xor_sync(0xffffffffu, v, o));
  return v;
}

// x[b,s,:] = emb[idx[b,s]] + pe[b]   (pe indexed by BATCH — faithful quirk)
__global__ void k_embed(const int* __restrict__ idx, const float* __restrict__ emb,
                        const float* __restrict__ pe) {
  int r = blockIdx.x, d = threadIdx.x;
  int b = r >> 9;
  g_x[r*DD+d] = emb[(long long)idx[r]*DD + d] + pe[b*DD+d];
}

// Generic batched SGEMM: C = A[MxK] @ B (B is KxN, or NxK if TB) (+bias)(+relu)
// Requires M%64==0, N%64==0, K%16==0 (true for all shapes used here).
template<bool TB, bool RELU, bool BIAS>
__global__ void k_gemm(const float* __restrict__ A, const float* __restrict__ Bm,
                       const float* __restrict__ bias, float* __restrict__ C,
                       int M, int N, int K, long long sA, long long sB, long long sC)
{
  A  += (long long)blockIdx.z * sA;
  Bm += (long long)blockIdx.z * sB;
  C  += (long long)blockIdx.z * sC;
  __shared__ float As[16][64];
  __shared__ float Bs[16][64];
  int tid = threadIdx.x;
  int tx = tid & 15, ty = tid >> 4;
  int row0 = blockIdx.y * 64;
  int col0 = blockIdx.x * 64;
  float acc[4][4] = {};
  for (int k0 = 0; k0 < K; k0 += 16) {
    { // A tile: As[kk][mm]
      int mm = tid >> 2, kk = (tid & 3) << 2;
      const float* ap = A + (long long)(row0+mm)*K + k0 + kk;
      #pragma unroll
      for (int j=0;j<4;j++) As[kk+j][mm] = ap[j];
    }
    if (TB) {
      int nn = tid >> 2, kk = (tid & 3) << 2;
      const float* bp = Bm + (long long)(col0+nn)*K + k0 + kk;
      #pragma unroll
      for (int j=0;j<4;j++) Bs[kk+j][nn] = bp[j];
    } else {
      int kk = tid >> 4, nn = (tid & 15) << 2;
      const float* bp = Bm + (long long)(k0+kk)*N + col0 + nn;
      #pragma unroll
      for (int j=0;j<4;j++) Bs[kk][nn+j] = bp[j];
    }
    __syncthreads();
    #pragma unroll
    for (int kk=0;kk<16;kk++) {
      float a[4], b[4];
      #pragma unroll
      for (int i=0;i<4;i++) a[i]=As[kk][(ty<<2)+i];
      #pragma unroll
      for (int j=0;j<4;j++) b[j]=Bs[kk][(tx<<2)+j];
      #pragma unroll
      for (int i=0;i<4;i++)
        #pragma unroll
        for (int j=0;j<4;j++) acc[i][j] = fmaf(a[i], b[j], acc[i][j]);
    }
    __syncthreads();
  }
  #pragma unroll
  for (int i=0;i<4;i++) {
    int rw = row0 + (ty<<2) + i;
    #pragma unroll
    for (int j=0;j<4;j++) {
      int cl = col0 + (tx<<2) + j;
      float v = acc[i][j];
      if (BIAS) v += bias[cl];
      if (RELU) v = fmaxf(v, 0.f);
      C[(long long)rw*N + cl] = v;
    }
  }
}

__global__ void k_zero() {
  int i = blockIdx.x*blockDim.x + threadIdx.x;
  if (i < BB*NB) g_cnt[i] = 0;
  if (i < BB*NB*DD) g_vb[i] = 0.f;
}

// LSH bucket id from q: proj_n = q . H[:,n] + H[D,n]; bit n = (proj >= 0)
__global__ void k_bucket(const float* __restrict__ hyp) {
  int r = blockIdx.x*blockDim.x + threadIdx.x;
  if (r >= RR) return;
  const float* q = g_q + r*DD;
  float p[NH];
  #pragma unroll
  for (int n=0;n<NH;n++) p[n] = hyp[DD*NH + n];   // bias row (appended ones)
  for (int d=0; d<DD; d++) {
    float qd = q[d];
    #pragma unroll
    for (int n=0;n<NH;n++) p[n] = fmaf(qd, hyp[d*NH+n], p[n]);
  }
  int bk = 0;
  #pragma unroll
  for (int n=0;n<NH;n++) if (p[n] >= 0.f) bk |= (1<<n);
  g_bucket[r] = bk;
  atomicAdd(&g_cnt[(r>>9)*NB + bk], 1);
}

// per-bucket v sums: vb[b][bucket][d] += v[b,s,d]
__global__ void k_vbucket() {
  int r = blockIdx.x, d = threadIdx.x;
  int b = r >> 9;
  int bk = g_bucket[r];
  atomicAdd(&g_vb[(b*NB+bk)*DD + d], g_v[r*DD+d]);
}

// Row pass over G: max -> E=exp(scale*G - M) -> segmented sums -> Z_i, A
// -> overwrite row in place with combined weights Wc[s,t] = E*(A - invZ[bt])
__global__ void k_rowpass() {
  int r = blockIdx.x;
  int b = r >> 9;
  int sl = r & 511;
  float* Erow = g_E + (long long)r * SS;
  __shared__ float sG[SS];
  __shared__ int   sBk[SS];
  __shared__ float sEsum[NB];
  __shared__ float sInvZ[NB];
  __shared__ float sred[8];
  __shared__ float sM, sEtot, sA;
  int tid = threadIdx.x;
  int lane = tid & 31, wid = tid >> 5;
  const int* bkb = g_bucket + b*SS;
  for (int t = tid; t < SS; t += 256) { sG[t] = Erow[t]; sBk[t] = bkb[t]; }
  if (tid < NB) sEsum[tid] = 0.f;
  __syncthreads();
  const float scale = 0.088388347648318447f; // 1/sqrt(128)
  // row max of scale*G (scale > 0 -> scale * max(G))
  float m = -1e30f;
  for (int t = tid; t < SS; t += 256) m = fmaxf(m, sG[t]);
  m = warpMax(m);
  if (!lane) sred[wid] = m;
  __syncthreads();
  if (tid == 0) {
    float mm = sred[0];
    #pragma unroll
    for (int i=1;i<8;i++) mm = fmaxf(mm, sred[i]);
    sM = mm;
  }
  __syncthreads();
  float M = sM * scale;
  // E pass + segmented sums
  float etot = 0.f;
  for (int t = tid; t < SS; t += 256) {
    float e = expf(fmaf(scale, sG[t], -M));
    sG[t] = e;               // reuse smem: now holds E
    etot += e;
    atomicAdd(&sEsum[sBk[t]], e);
  }
  etot = warpSum(etot);
  if (!lane) sred[wid] = etot;
  __syncthreads();
  if (tid == 0) {
    float s = 0.f;
    #pragma unroll
    for (int i=0;i<8;i++) s += sred[i];
    sEtot = s;
  }
  __syncthreads();
  int bs = sBk[sl];
  float u = expf(-M);        // masked entries contribute exp(0 - M)
  if (tid < NB) {
    float Z = sEtot - sEsum[tid] + (float)g_cnt[b*NB+tid] * u;
    sInvZ[tid] = 1.f / Z;
  }
  __syncthreads();
  if (tid < 32) {
    float av = (tid == bs) ? 0.f : sInvZ[tid];
    av = warpSum(av);
    if (tid == 0) sA = av;
  }
  __syncthreads();
  float A = sA;
  for (int t = tid; t < SS; t += 256) {
    int bt = sBk[t];
    float gg = (bt != bs) ? sInvZ[bt] : 0.f;
    Erow[t] = sG[t] * (A - gg);
  }
}

// attention output = acc + (1/512)*(Vsum - V_{bucket(s)}), then LayerNorm -> g_x
__global__ void k_attn_ln(const float* __restrict__ gam, const float* __restrict__ bet) {
  int r = blockIdx.x, d = threadIdx.x;
  int b = r >> 9;
  int bs = g_bucket[r];
  float vs = 0.f;
  #pragma unroll
  for (int i=0;i<NB;i++) vs += g_vb[(b*NB+i)*DD + d];
  float val = g_acc[r*DD+d] + (vs - g_vb[(b*NB+bs)*DD + d]) * (1.f/512.f);
  __shared__ float s1[4], s2[4];
  float su = warpSum(val), sq = warpSum(val*val);
  int lane = d & 31, wid = d >> 5;
  if (!lane) { s1[wid]=su; s2[wid]=sq; }
  __syncthreads();
  float tsum = s1[0]+s1[1]+s1[2]+s1[3];
  float tsq  = s2[0]+s2[1]+s2[2]+s2[3];
  float mu = tsum * (1.f/128.f);
  float var = tsq * (1.f/128.f) - mu*mu;
  g_x[r*DD+d] = (val-mu)*rsqrtf(var+1e-5f)*gam[d] + bet[d];
}

// x = LayerNorm(ffn_out + x)
__global__ void k_res_ln(const float* __restrict__ gam, const float* __restrict__ bet) {
  int r = blockIdx.x, d = threadIdx.x;
  float val = g_acc[r*DD+d] + g_x[r*DD+d];
  __shared__ float s1[4], s2[4];
  float su = warpSum(val), sq = warpSum(val*val);
  int lane = d & 31, wid = d >> 5;
  if (!lane) { s1[wid]=su; s2[wid]=sq; }
  __syncthreads();
  float tsum = s1[0]+s1[1]+s1[2]+s1[3];
  float tsq  = s2[0]+s2[1]+s2[2]+s2[3];
  float mu = tsum * (1.f/128.f);
  float var = tsq * (1.f/128.f) - mu*mu;
  g_x[r*DD+d] = (val-mu)*rsqrtf(var+1e-5f)*gam[d] + bet[d];
}

// out[b,:] = flatten(x[b]) @ Wm + bm   (Wm is [S*D, 6] row-major)
__global__ void k_out(const float* __restrict__ Wm, const float* __restrict__ bm,
                      float* __restrict__ out) {
  int b = blockIdx.x, tid = threadIdx.x;
  float acc[OO] = {};
  const float* xr = g_x + (long long)b*SS*DD;
  for (int j = tid; j < SS*DD; j += 256) {
    float xv = xr[j];
    const float* w = Wm + (long long)j*OO;
    #pragma unroll
    for (int o=0;o<OO;o++) acc[o] = fmaf(xv, w[o], acc[o]);
  }
  __shared__ float sred[256];
  for (int o=0;o<OO;o++) {
    sred[tid] = acc[o];
    __syncthreads();
    for (int st=128; st; st>>=1) {
      if (tid < st) sred[tid] += sred[tid+st];
      __syncthreads();
    }
    if (tid == 0) out[b*OO+o] = sred[0] + bm[o];
    __syncthreads();
  }
}

extern "C" void kernel_launch(void* const* d_in, const int* in_sizes, int n_in,
                              void* d_out, int out_size) {
  const int*   idx = (const int*)  d_in[0];
  const float* emb = (const float*)d_in[1];
  const float* pe  = (const float*)d_in[2];
  const float* hyp = (const float*)d_in[3];
  const float* Wq  = (const float*)d_in[4];
  const float* bq  = (const float*)d_in[5];
  const float* Wv  = (const float*)d_in[6];
  const float* bv  = (const float*)d_in[7];
  const float* lng = (const float*)d_in[8];
  const float* lnb = (const float*)d_in[9];
  const float* W1  = (const float*)d_in[10];
  const float* b1  = (const float*)d_in[11];
  const float* W2  = (const float*)d_in[12];
  const float* b2  = (const float*)d_in[13];
  const float* Wm  = (const float*)d_in[14];
  const float* bm  = (const float*)d_in[15];
  float* out = (float*)d_out;

  float *px,*pq,*pv,*pE,*ph,*pacc;
  cudaGetSymbolAddress((void**)&px,   g_x);
  cudaGetSymbolAddress((void**)&pq,   g_q);
  cudaGetSymbolAddress((void**)&pv,   g_v);
  cudaGetSymbolAddress((void**)&pE,   g_E);
  cudaGetSymbolAddress((void**)&ph,   g_h);
  cudaGetSymbolAddress((void**)&pacc, g_acc);

  k_embed<<<RR, DD>>>(idx, emb, pe);
  for (int e = 0; e < 2; e++) {
    // q, v projections
    k_gemm<false,false,true><<<dim3(2,64,1),256>>>(px, Wq, bq, pq, RR, DD, DD, 0,0,0);
    k_gemm<false,false,true><<<dim3(2,64,1),256>>>(px, Wv, bv, pv, RR, DD, DD, 0,0,0);
    // buckets + per-bucket v sums
    k_zero<<<(BB*NB*DD+255)/256,256>>>();
    k_bucket<<<(RR+127)/128,128>>>(hyp);
    k_vbucket<<<RR,DD>>>();
    // G = q @ q^T (batched)
    k_gemm<true,false,false><<<dim3(8,8,BB),256>>>(pq, pq, nullptr, pE, SS, SS, DD,
        (long long)SS*DD, (long long)SS*DD, (long long)SS*SS);
    // combined per-row softmax weights (in place)
    k_rowpass<<<RR,256>>>();
    // acc = Wc @ v (batched)
    k_gemm<false,false,false><<<dim3(2,8,BB),256>>>(pE, pv, nullptr, pacc, SS, DD, SS,
        (long long)SS*SS, (long long)SS*DD, (long long)SS*DD);
    // + uniform bucket term, then LN
    k_attn_ln<<<RR,DD>>>(lng, lnb);
    // FFN + residual + LN
    k_gemm<false,true ,true><<<dim3(8,64,1),256>>>(px, W1, b1, ph,   RR, HH, DD, 0,0,0);
    k_gemm<false,false,true><<<dim3(2,64,1),256>>>(ph, W2, b2, pacc, RR, DD, HH, 0,0,0);
    k_res_ln<<<RR,DD>>>(lng, lnb);
  }
  k_out<<<BB,256>>>(Wm, bm, out);
}

// round 6
// speedup vs baseline: 1.2994x; 1.2994x over previous
#include <cuda_runtime.h>
#include <math.h>

#define BB 8
#define SS 512
#define DD 128
#define HH 512
#define NB 32
#define NH 5
#define OO 6
#define RR (BB*SS)   // 4096 token rows

// -------- scratch (static device globals; no allocation at runtime) --------
__device__ float g_x[RR*DD];        // activations [B,S,D]
__device__ float g_q[RR*DD];
__device__ float g_v[RR*DD];
__device__ float g_E[BB*SS*SS];     // G, then E, then combined weights Wc (in place)
__device__ float g_h[RR*HH];        // FFN hidden
__device__ float g_acc[RR*DD];      // attention out / FFN out
__device__ int   g_bucket[RR];
__device__ int   g_cnt[BB*NB];
__device__ float g_vb[BB*NB*DD];    // per-bucket v sums
__device__ float g_vtot[BB*DD];     // total v sum per batch
__device__ float g_part[BB*8*OO];   // k_out partials

__device__ __forceinline__ float warpSum(float v){
  #pragma unroll
  for (int o=16;o;o>>=1) v += __shfl_xor_sync(0xffffffffu, v, o);
  return v;
}
__device__ __forceinline__ float warpMax(float v){
  #pragma unroll
  for (int o=16;o;o>>=1) v = fmaxf(v, __shfl_xor_sync(0xffffffffu, v, o));
  return v;
}

// x[b,s,:] = emb[idx[b,s]] + pe[b]   (pe indexed by BATCH — faithful quirk)
__global__ void k_embed(const int* __restrict__ idx, const float* __restrict__ emb,
                        const float* __restrict__ pe) {
  int r = blockIdx.x, d = threadIdx.x;
  int b = r >> 9;
  g_x[r*DD+d] = emb[(long long)idx[r]*DD + d] + pe[b*DD+d];
}

// ============ 128x128x16 double-buffered SGEMM, 8x8 micro-tile ============
template<bool TB, bool RELU, bool BIAS>
__global__ void __launch_bounds__(256) k_gemm128(
    const float* __restrict__ A, const float* __restrict__ Bm,
    const float* __restrict__ bias, float* __restrict__ C,
    int M, int N, int K, long long sA, long long sB, long long sC)
{
  A  += (long long)blockIdx.z * sA;
  Bm += (long long)blockIdx.z * sB;
  C  += (long long)blockIdx.z * sC;
  __shared__ float As[2][16][128];
  __shared__ float Bs[2][16][128];
  const int t = threadIdx.x;
  const int tx = t & 15, ty = t >> 4;
  const int row0 = blockIdx.y << 7, col0 = blockIdx.x << 7;
  const int ar = t >> 1, ak = (t & 1) << 3;      // A: 2 float4 along K per thread
  const int bk = t >> 4, bn = (t & 15) << 2;     // B(nonTB): 2 float4 along N
  const float* Ap  = A  + (long long)(row0 + ar) * K + ak;
  const float* BpT = Bm + (long long)(col0 + ar) * K + ak;
  const float* Bp  = Bm + (long long)bk * N + col0 + bn;

  float4 a0, a1, b0, b1;
  a0 = *(const float4*)Ap; a1 = *(const float4*)(Ap + 4);
  if (TB) { b0 = *(const float4*)BpT; b1 = *(const float4*)(BpT + 4); }
  else    { b0 = *(const float4*)Bp;  b1 = *(const float4*)(Bp + 64); }

  // stage buffer 0
  As[0][ak+0][ar]=a0.x; As[0][ak+1][ar]=a0.y; As[0][ak+2][ar]=a0.z; As[0][ak+3][ar]=a0.w;
  As[0][ak+4][ar]=a1.x; As[0][ak+5][ar]=a1.y; As[0][ak+6][ar]=a1.z; As[0][ak+7][ar]=a1.w;
  if (TB) {
    Bs[0][ak+0][ar]=b0.x; Bs[0][ak+1][ar]=b0.y; Bs[0][ak+2][ar]=b0.z; Bs[0][ak+3][ar]=b0.w;
    Bs[0][ak+4][ar]=b1.x; Bs[0][ak+5][ar]=b1.y; Bs[0][ak+6][ar]=b1.z; Bs[0][ak+7][ar]=b1.w;
  } else {
    *(float4*)&Bs[0][bk][bn]    = b0;
    *(float4*)&Bs[0][bk][bn+64] = b1;
  }
  __syncthreads();

  float acc[8][8];
  #pragma unroll
  for (int i=0;i<8;i++)
    #pragma unroll
    for (int j=0;j<8;j++) acc[i][j]=0.f;

  const int nk = K >> 4;
  for (int ki = 0; ; ki++) {
    const int cur = ki & 1;
    if (ki + 1 < nk) {
      const int k0 = (ki + 1) << 4;
      a0 = *(const float4*)(Ap + k0); a1 = *(const float4*)(Ap + k0 + 4);
      if (TB) { b0 = *(const float4*)(BpT + k0); b1 = *(const float4*)(BpT + k0 + 4); }
      else { const float* p = Bp + (long long)k0 * N; b0 = *(const float4*)p; b1 = *(const float4*)(p + 64); }
    }
    #pragma unroll
    for (int kk = 0; kk < 16; kk++) {
      float a[8], b[8];
      *(float4*)&a[0] = *(float4*)&As[cur][kk][ty<<3];
      *(float4*)&a[4] = *(float4*)&As[cur][kk][(ty<<3)+4];
      *(float4*)&b[0] = *(float4*)&Bs[cur][kk][tx<<3];
      *(float4*)&b[4] = *(float4*)&Bs[cur][kk][(tx<<3)+4];
      #pragma unroll
      for (int i=0;i<8;i++)
        #pragma unroll
        for (int j=0;j<8;j++) acc[i][j] = fmaf(a[i], b[j], acc[i][j]);
    }
    if (ki + 1 == nk) break;
    const int nxt = cur ^ 1;
    As[nxt][ak+0][ar]=a0.x; As[nxt][ak+1][ar]=a0.y; As[nxt][ak+2][ar]=a0.z; As[nxt][ak+3][ar]=a0.w;
    As[nxt][ak+4][ar]=a1.x; As[nxt][ak+5][ar]=a1.y; As[nxt][ak+6][ar]=a1.z; As[nxt][ak+7][ar]=a1.w;
    if (TB) {
      Bs[nxt][ak+0][ar]=b0.x; Bs[nxt][ak+1][ar]=b0.y; Bs[nxt][ak+2][ar]=b0.z; Bs[nxt][ak+3][ar]=b0.w;
      Bs[nxt][ak+4][ar]=b1.x; Bs[nxt][ak+5][ar]=b1.y; Bs[nxt][ak+6][ar]=b1.z; Bs[nxt][ak+7][ar]=b1.w;
    } else {
      *(float4*)&Bs[nxt][bk][bn]    = b0;
      *(float4*)&Bs[nxt][bk][bn+64] = b1;
    }
    __syncthreads();
  }

  #pragma unroll
  for (int i=0;i<8;i++) {
    const int rw = row0 + (ty<<3) + i;
    float* cp = C + (long long)rw * N + col0 + (tx<<3);
    float4 o0, o1;
    o0.x=acc[i][0]; o0.y=acc[i][1]; o0.z=acc[i][2]; o0.w=acc[i][3];
    o1.x=acc[i][4]; o1.y=acc[i][5]; o1.z=acc[i][6]; o1.w=acc[i][7];
    if (BIAS) {
      const float* bp = bias + col0 + (tx<<3);
      o0.x+=bp[0]; o0.y+=bp[1]; o0.z+=bp[2]; o0.w+=bp[3];
      o1.x+=bp[4]; o1.y+=bp[5]; o1.z+=bp[6]; o1.w+=bp[7];
    }
    if (RELU) {
      o0.x=fmaxf(o0.x,0.f); o0.y=fmaxf(o0.y,0.f); o0.z=fmaxf(o0.z,0.f); o0.w=fmaxf(o0.w,0.f);
      o1.x=fmaxf(o1.x,0.f); o1.y=fmaxf(o1.y,0.f); o1.z=fmaxf(o1.z,0.f); o1.w=fmaxf(o1.w,0.f);
    }
    *(float4*)cp = o0; *(float4*)(cp+4) = o1;
  }
}

// ============ 64x64x16 double-buffered SGEMM, 4x4 micro-tile ============
template<bool TB, bool RELU, bool BIAS>
__global__ void __launch_bounds__(256) k_gemm64(
    const float* __restrict__ A, const float* __restrict__ Bm,
    const float* __restrict__ bias, float* __restrict__ C,
    int M, int N, int K, long long sA, long long sB, long long sC)
{
  A  += (long long)blockIdx.z * sA;
  Bm += (long long)blockIdx.z * sB;
  C  += (long long)blockIdx.z * sC;
  __shared__ float As[2][16][64];
  __shared__ float Bs[2][16][64];
  const int t = threadIdx.x;
  const int tx = t & 15, ty = t >> 4;
  const int row0 = blockIdx.y << 6, col0 = blockIdx.x << 6;
  const int ar = t >> 2, ak = (t & 3) << 2;   // A: 1 float4 per thread
  const int bk = t >> 4, bn = (t & 15) << 2;  // B(nonTB): 1 float4
  const float* Ap  = A  + (long long)(row0 + ar) * K + ak;
  const float* BpT = Bm + (long long)(col0 + ar) * K + ak;
  const float* Bp  = Bm + (long long)bk * N + col0 + bn;

  float4 a4, b4;
  a4 = *(const float4*)Ap;
  if (TB) b4 = *(const float4*)BpT; else b4 = *(const float4*)Bp;

  As[0][ak+0][ar]=a4.x; As[0][ak+1][ar]=a4.y; As[0][ak+2][ar]=a4.z; As[0][ak+3][ar]=a4.w;
  if (TB) {
    Bs[0][ak+0][ar]=b4.x; Bs[0][ak+1][ar]=b4.y; Bs[0][ak+2][ar]=b4.z; Bs[0][ak+3][ar]=b4.w;
  } else {
    *(float4*)&Bs[0][bk][bn] = b4;
  }
  __syncthreads();

  float acc[4][4];
  #pragma unroll
  for (int i=0;i<4;i++)
    #pragma unroll
    for (int j=0;j<4;j++) acc[i][j]=0.f;

  const int nk = K >> 4;
  for (int ki = 0; ; ki++) {
    const int cur = ki & 1;
    if (ki + 1 < nk) {
      const int k0 = (ki + 1) << 4;
      a4 = *(const float4*)(Ap + k0);
      if (TB) b4 = *(const float4*)(BpT + k0);
      else    b4 = *(const float4*)(Bp + (long long)k0 * N);
    }
    #pragma unroll
    for (int kk = 0; kk < 16; kk++) {
      float a[4], b[4];
      *(float4*)&a[0] = *(float4*)&As[cur][kk][ty<<2];
      *(float4*)&b[0] = *(float4*)&Bs[cur][kk][tx<<2];
      #pragma unroll
      for (int i=0;i<4;i++)
        #pragma unroll
        for (int j=0;j<4;j++) acc[i][j] = fmaf(a[i], b[j], acc[i][j]);
    }
    if (ki + 1 == nk) break;
    const int nxt = cur ^ 1;
    As[nxt][ak+0][ar]=a4.x; As[nxt][ak+1][ar]=a4.y; As[nxt][ak+2][ar]=a4.z; As[nxt][ak+3][ar]=a4.w;
    if (TB) {
      Bs[nxt][ak+0][ar]=b4.x; Bs[nxt][ak+1][ar]=b4.y; Bs[nxt][ak+2][ar]=b4.z; Bs[nxt][ak+3][ar]=b4.w;
    } else {
      *(float4*)&Bs[nxt][bk][bn] = b4;
    }
    __syncthreads();
  }

  #pragma unroll
  for (int i=0;i<4;i++) {
    const int rw = row0 + (ty<<2) + i;
    float* cp = C + (long long)rw * N + col0 + (tx<<2);
    float4 o;
    o.x=acc[i][0]; o.y=acc[i][1]; o.z=acc[i][2]; o.w=acc[i][3];
    if (BIAS) {
      const float* bp = bias + col0 + (tx<<2);
      o.x+=bp[0]; o.y+=bp[1]; o.z+=bp[2]; o.w+=bp[3];
    }
    if (RELU) { o.x=fmaxf(o.x,0.f); o.y=fmaxf(o.y,0.f); o.z=fmaxf(o.z,0.f); o.w=fmaxf(o.w,0.f); }
    *(float4*)cp = o;
  }
}

// LSH bucket id from q: one warp per token row, coalesced q loads.
__global__ void k_bucket(const float* __restrict__ hyp) {
  int gw = (blockIdx.x * blockDim.x + threadIdx.x) >> 5;
  int lane = threadIdx.x & 31;
  if (gw >= RR) return;
  const float* q = g_q + gw * DD;
  float p[NH];
  #pragma unroll
  for (int n=0;n<NH;n++) p[n] = (lane == 0) ? hyp[DD*NH + n] : 0.f;  // bias row
  #pragma unroll
  for (int i=0;i<4;i++) {
    int d = lane + i*32;
    float qd = q[d];
    #pragma unroll
    for (int n=0;n<NH;n++) p[n] = fmaf(qd, hyp[d*NH+n], p[n]);
  }
  #pragma unroll
  for (int n=0;n<NH;n++) p[n] = warpSum(p[n]);
  if (lane == 0) {
    int bk = 0;
    #pragma unroll
    for (int n=0;n<NH;n++) if (p[n] >= 0.f) bk |= (1<<n);
    g_bucket[gw] = bk;
  }
}

// Direct per-(bucket,batch) v sum + count — no zeroing, no atomics.
__global__ void k_bsum() {
  int i = blockIdx.x;   // bucket
  int b = blockIdx.y;   // batch
  int d = threadIdx.x;  // 128
  __shared__ int sb[SS];
  for (int t = d; t < SS; t += DD) sb[t] = g_bucket[b*SS + t];
  __syncthreads();
  float acc = 0.f; int cnt = 0;
  const float* vbase = g_v + (long long)b*SS*DD + d;
  for (int s = 0; s < SS; s++) {
    if (sb[s] == i) { acc += vbase[s*DD]; cnt++; }
  }
  g_vb[(b*NB+i)*DD + d] = acc;
  if (d == 0) g_cnt[b*NB + i] = cnt;
}

__global__ void k_vtot() {
  int b = blockIdx.x, d = threadIdx.x;
  float s = 0.f;
  #pragma unroll
  for (int i=0;i<NB;i++) s += g_vb[(b*NB+i)*DD + d];
  g_vtot[b*DD + d] = s;
}

// Row pass over G: max -> E=exp(scale*G - M) -> segmented sums -> Z_i, A
// -> overwrite row in place with combined weights Wc[s,t] = E*(A - invZ[bt])
__global__ void k_rowpass() {
  int r = blockIdx.x;
  int b = r >> 9;
  int sl = r & 511;
  float* Erow = g_E + (long long)r * SS;
  __shared__ float sG[SS];
  __shared__ int   sBk[SS];
  __shared__ float sEsum[NB];
  __shared__ float sInvZ[NB];
  __shared__ float sred[8];
  __shared__ float sM, sEtot, sA;
  int tid = threadIdx.x;
  int lane = tid & 31, wid = tid >> 5;
  const int* bkb = g_bucket + b*SS;
  for (int t = tid; t < SS; t += 256) { sG[t] = Erow[t]; sBk[t] = bkb[t]; }
  if (tid < NB) sEsum[tid] = 0.f;
  __syncthreads();
  const float scale = 0.088388347648318447f; // 1/sqrt(128)
  float m = -1e30f;
  for (int t = tid; t < SS; t += 256) m = fmaxf(m, sG[t]);
  m = warpMax(m);
  if (!lane) sred[wid] = m;
  __syncthreads();
  if (tid == 0) {
    float mm = sred[0];
    #pragma unroll
    for (int i=1;i<8;i++) mm = fmaxf(mm, sred[i]);
    sM = mm;
  }
  __syncthreads();
  float M = sM * scale;
  float etot = 0.f;
  for (int t = tid; t < SS; t += 256) {
    float e = __expf(fmaf(scale, sG[t], -M));
    sG[t] = e;
    etot += e;
    atomicAdd(&sEsum[sBk[t]], e);
  }
  etot = warpSum(etot);
  if (!lane) sred[wid] = etot;
  __syncthreads();
  if (tid == 0) {
    float s = 0.f;
    #pragma unroll
    for (int i=0;i<8;i++) s += sred[i];
    sEtot = s;
  }
  __syncthreads();
  int bs = sBk[sl];
  float u = __expf(-M);
  if (tid < NB) {
    float Z = sEtot - sEsum[tid] + (float)g_cnt[b*NB+tid] * u;
    sInvZ[tid] = 1.f / Z;
  }
  __syncthreads();
  if (tid < 32) {
    float av = (tid == bs) ? 0.f : sInvZ[tid];
    av = warpSum(av);
    if (tid == 0) sA = av;
  }
  __syncthreads();
  float A = sA;
  for (int t = tid; t < SS; t += 256) {
    int bt = sBk[t];
    float gg = (bt != bs) ? sInvZ[bt] : 0.f;
    Erow[t] = sG[t] * (A - gg);
  }
}

// attention output = acc + (1/512)*(Vsum - V_{bucket(s)}), then LayerNorm -> g_x
__global__ void k_attn_ln(const float* __restrict__ gam, const float* __restrict__ bet) {
  int r = blockIdx.x, d = threadIdx.x;
  int b = r >> 9;
  int bs = g_bucket[r];
  float val = g_acc[r*DD+d] + (g_vtot[b*DD+d] - g_vb[(b*NB+bs)*DD + d]) * (1.f/512.f);
  __shared__ float s1[4], s2[4];
  float su = warpSum(val), sq = warpSum(val*val);
  int lane = d & 31, wid = d >> 5;
  if (!lane) { s1[wid]=su; s2[wid]=sq; }
  __syncthreads();
  float tsum = s1[0]+s1[1]+s1[2]+s1[3];
  float tsq  = s2[0]+s2[1]+s2[2]+s2[3];
  float mu = tsum * (1.f/128.f);
  float var = tsq * (1.f/128.f) - mu*mu;
  g_x[r*DD+d] = (val-mu)*rsqrtf(var+1e-5f)*gam[d] + bet[d];
}

// x = LayerNorm(ffn_out + x)
__global__ void k_res_ln(const float* __restrict__ gam, const float* __restrict__ bet) {
  int r = blockIdx.x, d = threadIdx.x;
  float val = g_acc[r*DD+d] + g_x[r*DD+d];
  __shared__ float s1[4], s2[4];
  float su = warpSum(val), sq = warpSum(val*val);
  int lane = d & 31, wid = d >> 5;
  if (!lane) { s1[wid]=su; s2[wid]=sq; }
  __syncthreads();
  float tsum = s1[0]+s1[1]+s1[2]+s1[3];
  float tsq  = s2[0]+s2[1]+s2[2]+s2[3];
  float mu = tsum * (1.f/128.f);
  float var = tsq * (1.f/128.f) - mu*mu;
  g_x[r*DD+d] = (val-mu)*rsqrtf(var+1e-5f)*gam[d] + bet[d];
}

// partial out: block (chunk c, batch b) reduces 8192 elements of x[b] @ Wm
__global__ void k_out1(const float* __restrict__ Wm) {
  int c = blockIdx.x, b = blockIdx.y;
  int tid = threadIdx.x;
  float acc[OO] = {};
  const float* xr = g_x + (long long)b*SS*DD;
  int base = c * 8192;
  for (int j = base + tid; j < base + 8192; j += 256) {
    float xv = xr[j];
    const float* w = Wm + (long long)j*OO;
    #pragma unroll
    for (int o=0;o<OO;o++) acc[o] = fmaf(xv, w[o], acc[o]);
  }
  __shared__ float sred[256];
  for (int o=0;o<OO;o++) {
    sred[tid] = acc[o];
    __syncthreads();
    for (int st=128; st; st>>=1) {
      if (tid < st) sred[tid] += sred[tid+st];
      __syncthreads();
    }
    if (tid == 0) g_part[(b*8+c)*OO+o] = sred[0];
    __syncthreads();
  }
}

__global__ void k_out2(const float* __restrict__ bm, float* __restrict__ out) {
  int tid = threadIdx.x;
  if (tid < BB*OO) {
    int b = tid / OO, o = tid % OO;
    float s = bm[o];
    #pragma unroll
    for (int c=0;c<8;c++) s += g_part[(b*8+c)*OO+o];
    out[b*OO+o] = s;
  }
}

extern "C" void kernel_launch(void* const* d_in, const int* in_sizes, int n_in,
                              void* d_out, int out_size) {
  const int*   idx = (const int*)  d_in[0];
  const float* emb = (const float*)d_in[1];
  const float* pe  = (const float*)d_in[2];
  const float* hyp = (const float*)d_in[3];
  const float* Wq  = (const float*)d_in[4];
  const float* bq  = (const float*)d_in[5];
  const float* Wv  = (const float*)d_in[6];
  const float* bv  = (const float*)d_in[7];
  const float* lng = (const float*)d_in[8];
  const float* lnb = (const float*)d_in[9];
  const float* W1  = (const float*)d_in[10];
  const float* b1  = (const float*)d_in[11];
  const float* W2  = (const float*)d_in[12];
  const float* b2  = (const float*)d_in[13];
  const float* Wm  = (const float*)d_in[14];
  const float* bm  = (const float*)d_in[15];
  float* out = (float*)d_out;

  float *px,*pq,*pv,*pE,*ph,*pacc;
  cudaGetSymbolAddress((void**)&px,   g_x);
  cudaGetSymbolAddress((void**)&pq,   g_q);
  cudaGetSymbolAddress((void**)&pv,   g_v);
  cudaGetSymbolAddress((void**)&pE,   g_E);
  cudaGetSymbolAddress((void**)&ph,   g_h);
  cudaGetSymbolAddress((void**)&pacc, g_acc);

  k_embed<<<RR, DD>>>(idx, emb, pe);
  for (int e = 0; e < 2; e++) {
    // q, v projections (fp32 — keeps LSH bucket bits exact)
    k_gemm64<false,false,true><<<dim3(2,64,1),256>>>(px, Wq, bq, pq, RR, DD, DD, 0,0,0);
    k_gemm64<false,false,true><<<dim3(2,64,1),256>>>(px, Wv, bv, pv, RR, DD, DD, 0,0,0);
    // buckets + per-bucket v sums (atomic-free)
    k_bucket<<<512,256>>>(hyp);
    k_bsum<<<dim3(NB,BB),DD>>>();
    k_vtot<<<BB,DD>>>();
    // G = q @ q^T (batched)
    k_gemm128<true,false,false><<<dim3(4,4,BB),256>>>(pq, pq, nullptr, pE, SS, SS, DD,
        (long long)SS*DD, (long long)SS*DD, (long long)SS*SS);
    // combined per-row softmax weights (in place)
    k_rowpass<<<RR,256>>>();
    // acc = Wc @ v (batched)
    k_gemm64<false,false,false><<<dim3(2,8,BB),256>>>(pE, pv, nullptr, pacc, SS, DD, SS,
        (long long)SS*SS, (long long)SS*DD, (long long)SS*DD);
    // + uniform bucket term, then LN
    k_attn_ln<<<RR,DD>>>(lng, lnb);
    // FFN + residual + LN
    k_gemm128<false,true ,true><<<dim3(4,32,1),256>>>(px, W1, b1, ph,   RR, HH, DD, 0,0,0);
    k_gemm64 <false,false,true><<<dim3(2,64,1),256>>>(ph, W2, b2, pacc, RR, DD, HH, 0,0,0);
    k_res_ln<<<RR,DD>>>(lng, lnb);
  }
  k_out1<<<dim3(8,BB),256>>>(Wm);
  k_out2<<<1,64>>>(bm, out);
}

// round 7
// speedup vs baseline: 1.3016x; 1.0017x over previous
#include <cuda_runtime.h>
#include <math.h>

#define BB 8
#define SS 512
#define DD 128
#define HH 512
#define NB 32
#define NH 5
#define OO 6
#define RR (BB*SS)   // 4096 token rows

// -------- scratch (static device globals; no allocation at runtime) --------
__device__ float g_x[RR*DD];        // activations [B,S,D]
__device__ float g_q[RR*DD];
__device__ float g_v[RR*DD];
__device__ float g_E[BB*SS*SS];     // G, then E, then combined weights Wc (in place)
__device__ float g_h[RR*HH];        // FFN hidden
__device__ float g_acc[2*RR*DD];    // attention / FFN out (2 split-K slices)
__device__ int   g_bucket[RR];
__device__ int   g_cnt[BB*NB];
__device__ float g_vb[BB*NB*DD];    // per-bucket v sums
__device__ float g_vtot[BB*DD];     // total v sum per batch
__device__ float g_part[BB*8*OO];   // k_out partials
__device__ float g_Wqv[DD*256];     // [128, 256] = [Wq | Wv]
__device__ float g_bqv[256];

__device__ __forceinline__ float warpSum(float v){
  #pragma unroll
  for (int o=16;o;o>>=1) v += __shfl_xor_sync(0xffffffffu, v, o);
  return v;
}
__device__ __forceinline__ float warpMax(float v){
  #pragma unroll
  for (int o=16;o;o>>=1) v = fmaxf(v, __shfl_xor_sync(0xffffffffu, v, o));
  return v;
}

// build combined [Wq|Wv] weight + bias (weights are launch-invariant inputs)
__global__ void k_prep(const float* __restrict__ Wq, const float* __restrict__ bq,
                       const float* __restrict__ Wv, const float* __restrict__ bv) {
  int i = blockIdx.x*blockDim.x + threadIdx.x;
  if (i < DD*256) {
    int d = i >> 8, j = i & 255;
    g_Wqv[i] = (j < DD) ? Wq[d*DD + j] : Wv[d*DD + j - DD];
  }
  if (i < 256) g_bqv[i] = (i < DD) ? bq[i] : bv[i - DD];
}

// x[b,s,:] = emb[idx[b,s]] + pe[b]   (pe indexed by BATCH — faithful quirk)
__global__ void k_embed(const int* __restrict__ idx, const float* __restrict__ emb,
                        const float* __restrict__ pe) {
  int r = blockIdx.x, d = threadIdx.x;
  int b = r >> 9;
  g_x[r*DD+d] = emb[(long long)idx[r]*DD + d] + pe[b*DD+d];
}

// ============ 128x128x16 double-buffered SGEMM, 8x8 micro-tile ============
template<bool TB, bool RELU, bool BIAS>
__global__ void __launch_bounds__(256) k_gemm128(
    const float* __restrict__ A, const float* __restrict__ Bm,
    const float* __restrict__ bias, float* __restrict__ C,
    int M, int N, int K, long long sA, long long sB, long long sC)
{
  A  += (long long)blockIdx.z * sA;
  Bm += (long long)blockIdx.z * sB;
  C  += (long long)blockIdx.z * sC;
  __shared__ float As[2][16][128];
  __shared__ float Bs[2][16][128];
  const int t = threadIdx.x;
  const int tx = t & 15, ty = t >> 4;
  const int row0 = blockIdx.y << 7, col0 = blockIdx.x << 7;
  const int ar = t >> 1, ak = (t & 1) << 3;
  const int bk = t >> 4, bn = (t & 15) << 2;
  const float* Ap  = A  + (long long)(row0 + ar) * K + ak;
  const float* BpT = Bm + (long long)(col0 + ar) * K + ak;
  const float* Bp  = Bm + (long long)bk * N + col0 + bn;

  float4 a0, a1, b0, b1;
  a0 = *(const float4*)Ap; a1 = *(const float4*)(Ap + 4);
  if (TB) { b0 = *(const float4*)BpT; b1 = *(const float4*)(BpT + 4); }
  else    { b0 = *(const float4*)Bp;  b1 = *(const float4*)(Bp + 64); }

  As[0][ak+0][ar]=a0.x; As[0][ak+1][ar]=a0.y; As[0][ak+2][ar]=a0.z; As[0][ak+3][ar]=a0.w;
  As[0][ak+4][ar]=a1.x; As[0][ak+5][ar]=a1.y; As[0][ak+6][ar]=a1.z; As[0][ak+7][ar]=a1.w;
  if (TB) {
    Bs[0][ak+0][ar]=b0.x; Bs[0][ak+1][ar]=b0.y; Bs[0][ak+2][ar]=b0.z; Bs[0][ak+3][ar]=b0.w;
    Bs[0][ak+4][ar]=b1.x; Bs[0][ak+5][ar]=b1.y; Bs[0][ak+6][ar]=b1.z; Bs[0][ak+7][ar]=b1.w;
  } else {
    *(float4*)&Bs[0][bk][bn]    = b0;
    *(float4*)&Bs[0][bk][bn+64] = b1;
  }
  __syncthreads();

  float acc[8][8];
  #pragma unroll
  for (int i=0;i<8;i++)
    #pragma unroll
    for (int j=0;j<8;j++) acc[i][j]=0.f;

  const int nk = K >> 4;
  for (int ki = 0; ; ki++) {
    const int cur = ki & 1;
    if (ki + 1 < nk) {
      const int k0 = (ki + 1) << 4;
      a0 = *(const float4*)(Ap + k0); a1 = *(const float4*)(Ap + k0 + 4);
      if (TB) { b0 = *(const float4*)(BpT + k0); b1 = *(const float4*)(BpT + k0 + 4); }
      else { const float* p = Bp + (long long)k0 * N; b0 = *(const float4*)p; b1 = *(const float4*)(p + 64); }
    }
    #pragma unroll
    for (int kk = 0; kk < 16; kk++) {
      float a[8], b[8];
      *(float4*)&a[0] = *(float4*)&As[cur][kk][ty<<3];
      *(float4*)&a[4] = *(float4*)&As[cur][kk][(ty<<3)+4];
      *(float4*)&b[0] = *(float4*)&Bs[cur][kk][tx<<3];
      *(float4*)&b[4] = *(float4*)&Bs[cur][kk][(tx<<3)+4];
      #pragma unroll
      for (int i=0;i<8;i++)
        #pragma unroll
        for (int j=0;j<8;j++) acc[i][j] = fmaf(a[i], b[j], acc[i][j]);
    }
    if (ki + 1 == nk) break;
    const int nxt = cur ^ 1;
    As[nxt][ak+0][ar]=a0.x; As[nxt][ak+1][ar]=a0.y; As[nxt][ak+2][ar]=a0.z; As[nxt][ak+3][ar]=a0.w;
    As[nxt][ak+4][ar]=a1.x; As[nxt][ak+5][ar]=a1.y; As[nxt][ak+6][ar]=a1.z; As[nxt][ak+7][ar]=a1.w;
    if (TB) {
      Bs[nxt][ak+0][ar]=b0.x; Bs[nxt][ak+1][ar]=b0.y; Bs[nxt][ak+2][ar]=b0.z; Bs[nxt][ak+3][ar]=b0.w;
      Bs[nxt][ak+4][ar]=b1.x; Bs[nxt][ak+5][ar]=b1.y; Bs[nxt][ak+6][ar]=b1.z; Bs[nxt][ak+7][ar]=b1.w;
    } else {
      *(float4*)&Bs[nxt][bk][bn]    = b0;
      *(float4*)&Bs[nxt][bk][bn+64] = b1;
    }
    __syncthreads();
  }

  #pragma unroll
  for (int i=0;i<8;i++) {
    const int rw = row0 + (ty<<3) + i;
    float* cp = C + (long long)rw * N + col0 + (tx<<3);
    float4 o0, o1;
    o0.x=acc[i][0]; o0.y=acc[i][1]; o0.z=acc[i][2]; o0.w=acc[i][3];
    o1.x=acc[i][4]; o1.y=acc[i][5]; o1.z=acc[i][6]; o1.w=acc[i][7];
    if (BIAS) {
      const float* bp = bias + col0 + (tx<<3);
      o0.x+=bp[0]; o0.y+=bp[1]; o0.z+=bp[2]; o0.w+=bp[3];
      o1.x+=bp[4]; o1.y+=bp[5]; o1.z+=bp[6]; o1.w+=bp[7];
    }
    if (RELU) {
      o0.x=fmaxf(o0.x,0.f); o0.y=fmaxf(o0.y,0.f); o0.z=fmaxf(o0.z,0.f); o0.w=fmaxf(o0.w,0.f);
      o1.x=fmaxf(o1.x,0.f); o1.y=fmaxf(o1.y,0.f); o1.z=fmaxf(o1.z,0.f); o1.w=fmaxf(o1.w,0.f);
    }
    *(float4*)cp = o0; *(float4*)(cp+4) = o1;
  }
}

// ===== 128(M)x64(N)x16 double-buffered SGEMM, 8x4 micro-tile, 256 thr =====
// SPLIT2: blockIdx.z packs (batch, kslice); slice offsets applied to A/B,
//         C written to slice*sSlice (partials summed by the consumer).
// SPLITQV: epilogue scatters cols <128 -> g_q, >=128 -> g_v (C unused).
template<bool SPLIT2, bool SPLITQV, bool RELU, bool BIAS>
__global__ void __launch_bounds__(256) k_gemmS(
    const float* __restrict__ A, const float* __restrict__ Bm,
    const float* __restrict__ bias, float* __restrict__ C,
    int N, int K, int lda, long long sA, long long sB, long long sC, long long sSlice)
{
  int zb = blockIdx.z, sl = 0;
  if (SPLIT2) { sl = zb & 1; zb >>= 1; }
  A  += (long long)zb * sA;
  Bm += (long long)zb * sB;
  C  += (long long)zb * sC;
  if (SPLIT2) {
    A  += (long long)sl * K;          // K = slice length; A row stride = lda
    Bm += (long long)sl * K * N;
    C  += (long long)sl * sSlice;
  }
  __shared__ float As[2][16][128];
  __shared__ float Bs[2][16][64];
  const int t = threadIdx.x;
  const int tx = t & 15, ty = t >> 4;
  const int row0 = blockIdx.y << 7, col0 = blockIdx.x << 6;
  const int ar = t >> 1, ak = (t & 1) << 3;     // A: 2 float4 per thread
  const int bk = t >> 4, bn = (t & 15) << 2;    // B: 1 float4 per thread
  const float* Ap = A  + (long long)(row0 + ar) * lda + ak;
  const float* Bp = Bm + (long long)bk * N + col0 + bn;

  float4 a0, a1, b4;
  a0 = *(const float4*)Ap; a1 = *(const float4*)(Ap + 4);
  b4 = *(const float4*)Bp;

  As[0][ak+0][ar]=a0.x; As[0][ak+1][ar]=a0.y; As[0][ak+2][ar]=a0.z; As[0][ak+3][ar]=a0.w;
  As[0][ak+4][ar]=a1.x; As[0][ak+5][ar]=a1.y; As[0][ak+6][ar]=a1.z; As[0][ak+7][ar]=a1.w;
  *(float4*)&Bs[0][bk][bn] = b4;
  __syncthreads();

  float acc[8][4];
  #pragma unroll
  for (int i=0;i<8;i++)
    #pragma unroll
    for (int j=0;j<4;j++) acc[i][j]=0.f;

  const int nk = K >> 4;
  for (int ki = 0; ; ki++) {
    const int cur = ki & 1;
    if (ki + 1 < nk) {
      const int k0 = (ki + 1) << 4;
      a0 = *(const float4*)(Ap + k0); a1 = *(const float4*)(Ap + k0 + 4);
      b4 = *(const float4*)(Bp + (long long)k0 * N);
    }
    #pragma unroll
    for (int kk = 0; kk < 16; kk++) {
      float a[8], b[4];
      *(float4*)&a[0] = *(float4*)&As[cur][kk][ty<<3];
      *(float4*)&a[4] = *(float4*)&As[cur][kk][(ty<<3)+4];
      *(float4*)&b[0] = *(float4*)&Bs[cur][kk][tx<<2];
      #pragma unroll
      for (int i=0;i<8;i++)
        #pragma unroll
        for (int j=0;j<4;j++) acc[i][j] = fmaf(a[i], b[j], acc[i][j]);
    }
    if (ki + 1 == nk) break;
    const int nxt = cur ^ 1;
    As[nxt][ak+0][ar]=a0.x; As[nxt][ak+1][ar]=a0.y; As[nxt][ak+2][ar]=a0.z; As[nxt][ak+3][ar]=a0.w;
    As[nxt][ak+4][ar]=a1.x; As[nxt][ak+5][ar]=a1.y; As[nxt][ak+6][ar]=a1.z; As[nxt][ak+7][ar]=a1.w;
    *(float4*)&Bs[nxt][bk][bn] = b4;
    __syncthreads();
  }

  #pragma unroll
  for (int i=0;i<8;i++) {
    const int rw = row0 + (ty<<3) + i;
    const int cl = col0 + (tx<<2);
    float4 o;
    o.x=acc[i][0]; o.y=acc[i][1]; o.z=acc[i][2]; o.w=acc[i][3];
    if (BIAS && (!SPLIT2 || sl == 0)) {
      const float* bp = bias + cl;
      o.x+=bp[0]; o.y+=bp[1]; o.z+=bp[2]; o.w+=bp[3];
    }
    if (RELU) { o.x=fmaxf(o.x,0.f); o.y=fmaxf(o.y,0.f); o.z=fmaxf(o.z,0.f); o.w=fmaxf(o.w,0.f); }
    if (SPLITQV) {
      if (cl < DD) *(float4*)&g_q[(long long)rw*DD + cl] = o;
      else         *(float4*)&g_v[(long long)rw*DD + cl - DD] = o;
    } else {
      *(float4*)(C + (long long)rw * N + cl) = o;
    }
  }
}

// LSH bucket id from q: one warp per token row, coalesced q loads.
__global__ void k_bucket(const float* __restrict__ hyp) {
  int gw = (blockIdx.x * blockDim.x + threadIdx.x) >> 5;
  int lane = threadIdx.x & 31;
  if (gw >= RR) return;
  const float* q = g_q + gw * DD;
  float p[NH];
  #pragma unroll
  for (int n=0;n<NH;n++) p[n] = (lane == 0) ? hyp[DD*NH + n] : 0.f;  // bias row
  #pragma unroll
  for (int i=0;i<4;i++) {
    int d = lane + i*32;
    float qd = q[d];
    #pragma unroll
    for (int n=0;n<NH;n++) p[n] = fmaf(qd, hyp[d*NH+n], p[n]);
  }
  #pragma unroll
  for (int n=0;n<NH;n++) p[n] = warpSum(p[n]);
  if (lane == 0) {
    int bk = 0;
    #pragma unroll
    for (int n=0;n<NH;n++) if (p[n] >= 0.f) bk |= (1<<n);
    g_bucket[gw] = bk;
  }
}

// Direct per-(bucket,batch) v sum + count — no zeroing, no atomics.
__global__ void k_bsum() {
  int i = blockIdx.x;   // bucket
  int b = blockIdx.y;   // batch
  int d = threadIdx.x;  // 128
  __shared__ int sb[SS];
  for (int t = d; t < SS; t += DD) sb[t] = g_bucket[b*SS + t];
  __syncthreads();
  float acc = 0.f; int cnt = 0;
  const float* vbase = g_v + (long long)b*SS*DD + d;
  for (int s = 0; s < SS; s++) {
    if (sb[s] == i) { acc += vbase[s*DD]; cnt++; }
  }
  g_vb[(b*NB+i)*DD + d] = acc;
  if (d == 0) g_cnt[b*NB + i] = cnt;
}

__global__ void k_vtot() {
  int b = blockIdx.x, d = threadIdx.x;
  float s = 0.f;
  #pragma unroll
  for (int i=0;i<NB;i++) s += g_vb[(b*NB+i)*DD + d];
  g_vtot[b*DD + d] = s;
}

// Row pass over G: max -> E=exp(scale*G - M) -> segmented sums -> Z_i, A
// -> overwrite row in place with combined weights Wc[s,t] = E*(A - invZ[bt])
__global__ void k_rowpass() {
  int r = blockIdx.x;
  int b = r >> 9;
  int sl = r & 511;
  float* Erow = g_E + (long long)r * SS;
  __shared__ float sG[SS];
  __shared__ int   sBk[SS];
  __shared__ float sEsum[NB];
  __shared__ float sInvZ[NB];
  __shared__ float sred[8];
  __shared__ float sM, sEtot, sA;
  int tid = threadIdx.x;
  int lane = tid & 31, wid = tid >> 5;
  const int* bkb = g_bucket + b*SS;
  if (tid < 128) {
    ((float4*)sG)[tid] = ((const float4*)Erow)[tid];
    ((int4*)sBk)[tid]  = ((const int4*)bkb)[tid];
  }
  if (tid < NB) sEsum[tid] = 0.f;
  __syncthreads();
  const float scale = 0.088388347648318447f; // 1/sqrt(128)
  float m = -1e30f;
  for (int t = tid; t < SS; t += 256) m = fmaxf(m, sG[t]);
  m = warpMax(m);
  if (!lane) sred[wid] = m;
  __syncthreads();
  if (tid == 0) {
    float mm = sred[0];
    #pragma unroll
    for (int i=1;i<8;i++) mm = fmaxf(mm, sred[i]);
    sM = mm;
  }
  __syncthreads();
  float M = sM * scale;
  float etot = 0.f;
  for (int t = tid; t < SS; t += 256) {
    float e = __expf(fmaf(scale, sG[t], -M));
    sG[t] = e;
    etot += e;
    atomicAdd(&sEsum[sBk[t]], e);
  }
  etot = warpSum(etot);
  if (!lane) sred[wid] = etot;
  __syncthreads();
  if (tid == 0) {
    float s = 0.f;
    #pragma unroll
    for (int i=0;i<8;i++) s += sred[i];
    sEtot = s;
  }
  __syncthreads();
  int bs = sBk[sl];
  float u = __expf(-M);
  if (tid < NB) {
    float Z = sEtot - sEsum[tid] + (float)g_cnt[b*NB+tid] * u;
    sInvZ[tid] = 1.f / Z;
  }
  __syncthreads();
  if (tid < 32) {
    float av = (tid == bs) ? 0.f : sInvZ[tid];
    av = warpSum(av);
    if (tid == 0) sA = av;
  }
  __syncthreads();
  float A = sA;
  if (tid < 128) {
    float4 o;
    float* og = &sG[tid<<2];
    int*   ob = &sBk[tid<<2];
    o.x = og[0] * (A - ((ob[0] != bs) ? sInvZ[ob[0]] : 0.f));
    o.y = og[1] * (A - ((ob[1] != bs) ? sInvZ[ob[1]] : 0.f));
    o.z = og[2] * (A - ((ob[2] != bs) ? sInvZ[ob[2]] : 0.f));
    o.w = og[3] * (A - ((ob[3] != bs) ? sInvZ[ob[3]] : 0.f));
    ((float4*)Erow)[tid] = o;
  }
}

// attention output = accA+accB + (1/512)*(Vsum - V_{bucket(s)}), then LayerNorm -> g_x
__global__ void k_attn_ln(const float* __restrict__ gam, const float* __restrict__ bet) {
  int r = blockIdx.x, d = threadIdx.x;
  int b = r >> 9;
  int bs = g_bucket[r];
  float val = g_acc[r*DD+d] + g_acc[RR*DD + r*DD+d]
            + (g_vtot[b*DD+d] - g_vb[(b*NB+bs)*DD + d]) * (1.f/512.f);
  __shared__ float s1[4], s2[4];
  float su = warpSum(val), sq = warpSum(val*val);
  int lane = d & 31, wid = d >> 5;
  if (!lane) { s1[wid]=su; s2[wid]=sq; }
  __syncthreads();
  float tsum = s1[0]+s1[1]+s1[2]+s1[3];
  float tsq  = s2[0]+s2[1]+s2[2]+s2[3];
  float mu = tsum * (1.f/128.f);
  float var = tsq * (1.f/128.f) - mu*mu;
  g_x[r*DD+d] = (val-mu)*rsqrtf(var+1e-5f)*gam[d] + bet[d];
}

// x = LayerNorm(ffnA+ffnB + x)
__global__ void k_res_ln(const float* __restrict__ gam, const float* __restrict__ bet) {
  int r = blockIdx.x, d = threadIdx.x;
  float val = g_acc[r*DD+d] + g_acc[RR*DD + r*DD+d] + g_x[r*DD+d];
  __shared__ float s1[4], s2[4];
  float su = warpSum(val), sq = warpSum(val*val);
  int lane = d & 31, wid = d >> 5;
  if (!lane) { s1[wid]=su; s2[wid]=sq; }
  __syncthreads();
  float tsum = s1[0]+s1[1]+s1[2]+s1[3];
  float tsq  = s2[0]+s2[1]+s2[2]+s2[3];
  float mu = tsum * (1.f/128.f);
  float var = tsq * (1.f/128.f) - mu*mu;
  g_x[r*DD+d] = (val-mu)*rsqrtf(var+1e-5f)*gam[d] + bet[d];
}

// partial out: block (chunk c, batch b) reduces 8192 elements of x[b] @ Wm
__global__ void k_out1(const float* __restrict__ Wm) {
  int c = blockIdx.x, b = blockIdx.y;
  int tid = threadIdx.x;
  float acc[OO] = {};
  const float* xr = g_x + (long long)b*SS*DD;
  int base = c * 8192;
  for (int j = base + tid; j < base + 8192; j += 256) {
    float xv = xr[j];
    const float* w = Wm + (long long)j*OO;
    #pragma unroll
    for (int o=0;o<OO;o++) acc[o] = fmaf(xv, w[o], acc[o]);
  }
  __shared__ float sred[256];
  for (int o=0;o<OO;o++) {
    sred[tid] = acc[o];
    __syncthreads();
    for (int st=128; st; st>>=1) {
      if (tid < st) sred[tid] += sred[tid+st];
      __syncthreads();
    }
    if (tid == 0) g_part[(b*8+c)*OO+o] = sred[0];
    __syncthreads();
  }
}

__global__ void k_out2(const float* __restrict__ bm, float* __restrict__ out) {
  int tid = threadIdx.x;
  if (tid < BB*OO) {
    int b = tid / OO, o = tid % OO;
    float s = bm[o];
    #pragma unroll
    for (int c=0;c<8;c++) s += g_part[(b*8+c)*OO+o];
    out[b*OO+o] = s;
  }
}

extern "C" void kernel_launch(void* const* d_in, const int* in_sizes, int n_in,
                              void* d_out, int out_size) {
  const int*   idx = (const int*)  d_in[0];
  const float* emb = (const float*)d_in[1];
  const float* pe  = (const float*)d_in[2];
  const float* hyp = (const float*)d_in[3];
  const float* Wq  = (const float*)d_in[4];
  const float* bq  = (const float*)d_in[5];
  const float* Wv  = (const float*)d_in[6];
  const float* bv  = (const float*)d_in[7];
  const float* lng = (const float*)d_in[8];
  const float* lnb = (const float*)d_in[9];
  const float* W1  = (const float*)d_in[10];
  const float* b1  = (const float*)d_in[11];
  const float* W2  = (const float*)d_in[12];
  const float* b2  = (const float*)d_in[13];
  const float* Wm  = (const float*)d_in[14];
  const float* bm  = (const float*)d_in[15];
  float* out = (float*)d_out;

  float *px,*pq,*pv,*pE,*ph,*pacc,*pWqv,*pbqv;
  cudaGetSymbolAddress((void**)&px,   g_x);
  cudaGetSymbolAddress((void**)&pq,   g_q);
  cudaGetSymbolAddress((void**)&pv,   g_v);
  cudaGetSymbolAddress((void**)&pE,   g_E);
  cudaGetSymbolAddress((void**)&ph,   g_h);
  cudaGetSymbolAddress((void**)&pacc, g_acc);
  cudaGetSymbolAddress((void**)&pWqv, g_Wqv);
  cudaGetSymbolAddress((void**)&pbqv, g_bqv);

  k_prep<<<128,256>>>(Wq, bq, Wv, bv);
  k_embed<<<RR, DD>>>(idx, emb, pe);
  for (int e = 0; e < 2; e++) {
    // fused q|v projection: [4096,128] @ [128,256] -> scatter to g_q/g_v
    k_gemmS<false,true,false,true><<<dim3(4,32,1),256>>>(
        px, pWqv, pbqv, nullptr, 256, DD, DD, 0,0,0,0);
    // buckets + per-bucket v sums (atomic-free)
    k_bucket<<<512,256>>>(hyp);
    k_bsum<<<dim3(NB,BB),DD>>>();
    k_vtot<<<BB,DD>>>();
    // G = q @ q^T (batched)
    k_gemm128<true,false,false><<<dim3(4,4,BB),256>>>(pq, pq, nullptr, pE, SS, SS, DD,
        (long long)SS*DD, (long long)SS*DD, (long long)SS*SS);
    // combined per-row softmax weights (in place)
    k_rowpass<<<RR,256>>>();
    // acc = Wc @ v (batched, split-K=2 -> two partial buffers)
    k_gemmS<true,false,false,false><<<dim3(2,4,BB*2),256>>>(
        pE, pv, nullptr, pacc, DD, SS/2, SS,
        (long long)SS*SS, (long long)SS*DD, (long long)SS*DD, (long long)RR*DD);
    // + uniform bucket term, then LN
    k_attn_ln<<<RR,DD>>>(lng, lnb);
    // FFN + residual + LN
    k_gemm128<false,true ,true><<<dim3(4,32,1),256>>>(px, W1, b1, ph, RR, HH, DD, 0,0,0);
    k_gemmS<true,false,false,true><<<dim3(2,32,2),256>>>(
        ph, W2, b2, pacc, DD, HH/2, HH, 0,0,0, (long long)RR*DD);
    k_res_ln<<<RR,DD>>>(lng, lnb);
  }
  k_out1<<<dim3(8,BB),256>>>(Wm);
  k_out2<<<1,64>>>(bm, out);
}

// round 8
// speedup vs baseline: 1.6746x; 1.2865x over previous
#include <cuda_runtime.h>
#include <math.h>
#include <stdint.h>

#define BB 8
#define SS 512
#define DD 128
#define HH 512
#define NB 32
#define NH 5
#define OO 6
#define RR (BB*SS)   // 4096 token rows

// -------- scratch (static device globals; no allocation at runtime) --------
__device__ float g_x[RR*DD];        // activations [B,S,D]
__device__ float g_q[RR*DD];
__device__ float g_v[RR*DD];
__device__ float g_E[BB*SS*SS];     // G, then combined weights Wc (in place)
__device__ float g_h[RR*HH];        // FFN hidden
__device__ float g_acc[4*RR*DD];    // attention / FFN out (4 split-K slices)
__device__ int   g_bucket[RR];
__device__ int   g_cnt[BB*NB];
__device__ float g_vb[BB*NB*DD];    // per-bucket v sums
__device__ float g_vtot[BB*DD];     // total v sum per batch
__device__ float g_part[BB*8*OO];   // k_out partials
__device__ float g_Wqv[DD*256];     // [128, 256] = [Wq | Wv]
__device__ float g_bqv[256];

__device__ __forceinline__ float warpSum(float v){
  #pragma unroll
  for (int o=16;o;o>>=1) v += __shfl_xor_sync(0xffffffffu, v, o);
  return v;
}
__device__ __forceinline__ float warpMax(float v){
  #pragma unroll
  for (int o=16;o;o>>=1) v = fmaxf(v, __shfl_xor_sync(0xffffffffu, v, o));
  return v;
}
__device__ __forceinline__ uint32_t tf32(float x){
  uint32_t u; asm("cvt.rna.tf32.f32 %0, %1;" : "=r"(u) : "f"(x)); return u;
}

// build combined [Wq|Wv] weight + bias (weights are launch-invariant inputs)
__global__ void k_prep(const float* __restrict__ Wq, const float* __restrict__ bq,
                       const float* __restrict__ Wv, const float* __restrict__ bv) {
  int i = blockIdx.x*blockDim.x + threadIdx.x;
  if (i < DD*256) {
    int d = i >> 8, j = i & 255;
    g_Wqv[i] = (j < DD) ? Wq[d*DD + j] : Wv[d*DD + j - DD];
  }
  if (i < 256) g_bqv[i] = (i < DD) ? bq[i] : bv[i - DD];
}

// x[b,s,:] = emb[idx[b,s]] + pe[b]   (pe indexed by BATCH — faithful quirk)
__global__ void k_embed(const int* __restrict__ idx, const float* __restrict__ emb,
                        const float* __restrict__ pe) {
  int r = blockIdx.x, d = threadIdx.x;
  int b = r >> 9;
  g_x[r*DD+d] = emb[(long long)idx[r]*DD + d] + pe[b*DD+d];
}

// =================== TF32 tensor-core GEMM, 128x128 tile ===================
// C = A[M x Ktot] @ B  (TB: B is [N x Ktot] row-major; else [Ktot x N] row-major)
// Each CTA consumes exactly K=128 (one slice). NSLICE>1: blockIdx.z packs
// (batch, slice); slice s uses A cols [s*128,(s+1)*128), B rows likewise,
// writes C + s*sSlice (partials summed by the consumer). Bias on slice 0 only.
#define LSTR 136   // smem row stride in words; 136 % 32 == 8 -> conflict-free frags
template<bool TB, bool RELU, bool BIAS, int NSLICE>
__global__ void __launch_bounds__(256) k_mma(
    const float* __restrict__ A, const float* __restrict__ Bm,
    const float* __restrict__ bias, float* __restrict__ C,
    int N, int lda, int ldb,
    long long sA, long long sB, long long sC, long long sSlice)
{
  const int zb = blockIdx.z / NSLICE, sl = blockIdx.z % NSLICE;
  A  += (long long)zb*sA + (long long)sl*128;
  Bm += (long long)zb*sB;
  if (!TB) Bm += (long long)sl*128*ldb;
  C  += (long long)zb*sC + (long long)sl*sSlice;

  __shared__ uint32_t As[2][16*LSTR];
  __shared__ uint32_t Bs[2][16*LSTR];
  const int t = threadIdx.x;
  const int row0 = blockIdx.y << 7, col0 = blockIdx.x << 7;
  // staging indices
  const int ar = t >> 1, ak = (t & 1) << 3;     // A (and TB-B): 2 float4 along K
  const int bk = t >> 4, bn = (t & 15) << 2;    // nonTB-B: 2 float4 along N
  const float* Ap  = A  + (long long)(row0 + ar) * lda + ak;
  const float* BpT = Bm + (long long)(col0 + ar) * ldb + ak;
  const float* Bp  = Bm + (long long)bk * ldb + col0 + bn;

  float4 pa0, pa1, pb0, pb1;
  pa0 = *(const float4*)Ap; pa1 = *(const float4*)(Ap + 4);
  if (TB) { pb0 = *(const float4*)BpT; pb1 = *(const float4*)(BpT + 4); }
  else    { pb0 = *(const float4*)Bp;  pb1 = *(const float4*)(Bp + 64); }

  // stage buffer 0
  {
    uint32_t* as = As[0]; uint32_t* bs = Bs[0];
    as[(ak+0)*LSTR+ar]=tf32(pa0.x); as[(ak+1)*LSTR+ar]=tf32(pa0.y);
    as[(ak+2)*LSTR+ar]=tf32(pa0.z); as[(ak+3)*LSTR+ar]=tf32(pa0.w);
    as[(ak+4)*LSTR+ar]=tf32(pa1.x); as[(ak+5)*LSTR+ar]=tf32(pa1.y);
    as[(ak+6)*LSTR+ar]=tf32(pa1.z); as[(ak+7)*LSTR+ar]=tf32(pa1.w);
    if (TB) {
      bs[(ak+0)*LSTR+ar]=tf32(pb0.x); bs[(ak+1)*LSTR+ar]=tf32(pb0.y);
      bs[(ak+2)*LSTR+ar]=tf32(pb0.z); bs[(ak+3)*LSTR+ar]=tf32(pb0.w);
      bs[(ak+4)*LSTR+ar]=tf32(pb1.x); bs[(ak+5)*LSTR+ar]=tf32(pb1.y);
      bs[(ak+6)*LSTR+ar]=tf32(pb1.z); bs[(ak+7)*LSTR+ar]=tf32(pb1.w);
    } else {
      *(uint4*)&bs[bk*LSTR+bn]    = make_uint4(tf32(pb0.x),tf32(pb0.y),tf32(pb0.z),tf32(pb0.w));
      *(uint4*)&bs[bk*LSTR+bn+64] = make_uint4(tf32(pb1.x),tf32(pb1.y),tf32(pb1.z),tf32(pb1.w));
    }
  }
  __syncthreads();

  float acc[4][4][4];
  #pragma unroll
  for (int i=0;i<4;i++)
    #pragma unroll
    for (int j=0;j<4;j++)
      #pragma unroll
      for (int k=0;k<4;k++) acc[i][j][k]=0.f;

  const int lane = t & 31, g = lane >> 2, tg = lane & 3;
  const int wid = t >> 5;
  const int mb = (wid >> 2) * 64;   // warpRow in {0,1}
  const int nb = (wid & 3) * 32;    // warpCol in {0..3}

  for (int ki = 0; ; ki++) {
    const int cur = ki & 1;
    if (ki < 7) {
      const int k0 = (ki + 1) << 4;
      pa0 = *(const float4*)(Ap + k0); pa1 = *(const float4*)(Ap + k0 + 4);
      if (TB) { pb0 = *(const float4*)(BpT + k0); pb1 = *(const float4*)(BpT + k0 + 4); }
      else { const float* p = Bp + (long long)k0 * ldb; pb0 = *(const float4*)p; pb1 = *(const float4*)(p + 64); }
    }
    const uint32_t* as = As[cur];
    const uint32_t* bs = Bs[cur];
    #pragma unroll
    for (int kh = 0; kh < 2; kh++) {
      const int k0 = kh * 8;
      uint32_t af[4][4], bf[4][2];
      #pragma unroll
      for (int mt = 0; mt < 4; mt++) {
        int base = (k0 + tg) * LSTR + mb + mt*16 + g;
        af[mt][0] = as[base];            // (m=g,     k=tg)
        af[mt][1] = as[base + 8];        // (m=g+8,   k=tg)
        af[mt][2] = as[base + 4*LSTR];   // (m=g,     k=tg+4)
        af[mt][3] = as[base + 4*LSTR+8]; // (m=g+8,   k=tg+4)
      }
      #pragma unroll
      for (int nt = 0; nt < 4; nt++) {
        int base = (k0 + tg) * LSTR + nb + nt*8 + g;
        bf[nt][0] = bs[base];            // (k=tg,   n=g)
        bf[nt][1] = bs[base + 4*LSTR];   // (k=tg+4, n=g)
      }
      #pragma unroll
      for (int mt = 0; mt < 4; mt++)
        #pragma unroll
        for (int nt = 0; nt < 4; nt++) {
          asm volatile(
            "mma.sync.aligned.m16n8k8.row.col.f32.tf32.tf32.f32 "
            "{%0,%1,%2,%3}, {%4,%5,%6,%7}, {%8,%9}, {%0,%1,%2,%3};"
            : "+f"(acc[mt][nt][0]), "+f"(acc[mt][nt][1]),
              "+f"(acc[mt][nt][2]), "+f"(acc[mt][nt][3])
            : "r"(af[mt][0]), "r"(af[mt][1]), "r"(af[mt][2]), "r"(af[mt][3]),
              "r"(bf[nt][0]), "r"(bf[nt][1]));
        }
    }
    if (ki == 7) break;
    const int nxt = cur ^ 1;
    uint32_t* asw = As[nxt]; uint32_t* bsw = Bs[nxt];
    asw[(ak+0)*LSTR+ar]=tf32(pa0.x); asw[(ak+1)*LSTR+ar]=tf32(pa0.y);
    asw[(ak+2)*LSTR+ar]=tf32(pa0.z); asw[(ak+3)*LSTR+ar]=tf32(pa0.w);
    asw[(ak+4)*LSTR+ar]=tf32(pa1.x); asw[(ak+5)*LSTR+ar]=tf32(pa1.y);
    asw[(ak+6)*LSTR+ar]=tf32(pa1.z); asw[(ak+7)*LSTR+ar]=tf32(pa1.w);
    if (TB) {
      bsw[(ak+0)*LSTR+ar]=tf32(pb0.x); bsw[(ak+1)*LSTR+ar]=tf32(pb0.y);
      bsw[(ak+2)*LSTR+ar]=tf32(pb0.z); bsw[(ak+3)*LSTR+ar]=tf32(pb0.w);
      bsw[(ak+4)*LSTR+ar]=tf32(pb1.x); bsw[(ak+5)*LSTR+ar]=tf32(pb1.y);
      bsw[(ak+6)*LSTR+ar]=tf32(pb1.z); bsw[(ak+7)*LSTR+ar]=tf32(pb1.w);
    } else {
      *(uint4*)&bsw[bk*LSTR+bn]    = make_uint4(tf32(pb0.x),tf32(pb0.y),tf32(pb0.z),tf32(pb0.w));
      *(uint4*)&bsw[bk*LSTR+bn+64] = make_uint4(tf32(pb1.x),tf32(pb1.y),tf32(pb1.z),tf32(pb1.w));
    }
    __syncthreads();
  }

  // epilogue
  #pragma unroll
  for (int mt = 0; mt < 4; mt++) {
    const int r0 = row0 + mb + mt*16 + g;
    #pragma unroll
    for (int nt = 0; nt < 4; nt++) {
      const int c = col0 + nb + nt*8 + 2*tg;
      float d0 = acc[mt][nt][0], d1 = acc[mt][nt][1];
      float d2 = acc[mt][nt][2], d3 = acc[mt][nt][3];
      if (BIAS && sl == 0) {
        float bz0 = bias[c], bz1 = bias[c+1];
        d0 += bz0; d1 += bz1; d2 += bz0; d3 += bz1;
      }
      if (RELU) {
        d0=fmaxf(d0,0.f); d1=fmaxf(d1,0.f); d2=fmaxf(d2,0.f); d3=fmaxf(d3,0.f);
      }
      float2 lo; lo.x=d0; lo.y=d1;
      float2 hi; hi.x=d2; hi.y=d3;
      *(float2*)(C + (long long)r0*N + c)     = lo;
      *(float2*)(C + (long long)(r0+8)*N + c) = hi;
    }
  }
}

// ===== fp32 128x64 SGEMM for q|v projection (exact; bucket bits depend on it)
__global__ void __launch_bounds__(256) k_qv(
    const float* __restrict__ A, const float* __restrict__ Bm,
    const float* __restrict__ bias)
{
  const int N = 256, K = DD, lda = DD;
  __shared__ float As[2][16][128];
  __shared__ float Bs[2][16][64];
  const int t = threadIdx.x;
  const int tx = t & 15, ty = t >> 4;
  const int row0 = blockIdx.y << 7, col0 = blockIdx.x << 6;
  const int ar = t >> 1, ak = (t & 1) << 3;
  const int bk = t >> 4, bn = (t & 15) << 2;
  const float* Ap = A  + (long long)(row0 + ar) * lda + ak;
  const float* Bp = Bm + (long long)bk * N + col0 + bn;

  float4 a0, a1, b4;
  a0 = *(const float4*)Ap; a1 = *(const float4*)(Ap + 4);
  b4 = *(const float4*)Bp;

  As[0][ak+0][ar]=a0.x; As[0][ak+1][ar]=a0.y; As[0][ak+2][ar]=a0.z; As[0][ak+3][ar]=a0.w;
  As[0][ak+4][ar]=a1.x; As[0][ak+5][ar]=a1.y; As[0][ak+6][ar]=a1.z; As[0][ak+7][ar]=a1.w;
  *(float4*)&Bs[0][bk][bn] = b4;
  __syncthreads();

  float acc[8][4];
  #pragma unroll
  for (int i=0;i<8;i++)
    #pragma unroll
    for (int j=0;j<4;j++) acc[i][j]=0.f;

  const int nk = K >> 4;
  for (int ki = 0; ; ki++) {
    const int cur = ki & 1;
    if (ki + 1 < nk) {
      const int k0 = (ki + 1) << 4;
      a0 = *(const float4*)(Ap + k0); a1 = *(const float4*)(Ap + k0 + 4);
      b4 = *(const float4*)(Bp + (long long)k0 * N);
    }
    #pragma unroll
    for (int kk = 0; kk < 16; kk++) {
      float a[8], b[4];
      *(float4*)&a[0] = *(float4*)&As[cur][kk][ty<<3];
      *(float4*)&a[4] = *(float4*)&As[cur][kk][(ty<<3)+4];
      *(float4*)&b[0] = *(float4*)&Bs[cur][kk][tx<<2];
      #pragma unroll
      for (int i=0;i<8;i++)
        #pragma unroll
        for (int j=0;j<4;j++) acc[i][j] = fmaf(a[i], b[j], acc[i][j]);
    }
    if (ki + 1 == nk) break;
    const int nxt = cur ^ 1;
    As[nxt][ak+0][ar]=a0.x; As[nxt][ak+1][ar]=a0.y; As[nxt][ak+2][ar]=a0.z; As[nxt][ak+3][ar]=a0.w;
    As[nxt][ak+4][ar]=a1.x; As[nxt][ak+5][ar]=a1.y; As[nxt][ak+6][ar]=a1.z; As[nxt][ak+7][ar]=a1.w;
    *(float4*)&Bs[nxt][bk][bn] = b4;
    __syncthreads();
  }

  #pragma unroll
  for (int i=0;i<8;i++) {
    const int rw = row0 + (ty<<3) + i;
    const int cl = col0 + (tx<<2);
    float4 o;
    o.x=acc[i][0]; o.y=acc[i][1]; o.z=acc[i][2]; o.w=acc[i][3];
    const float* bp = bias + cl;
    o.x+=bp[0]; o.y+=bp[1]; o.z+=bp[2]; o.w+=bp[3];
    if (cl < DD) *(float4*)&g_q[(long long)rw*DD + cl] = o;
    else         *(float4*)&g_v[(long long)rw*DD + cl - DD] = o;
  }
}

// LSH bucket id from q: one warp per token row, coalesced q loads.
__global__ void k_bucket(const float* __restrict__ hyp) {
  int gw = (blockIdx.x * blockDim.x + threadIdx.x) >> 5;
  int lane = threadIdx.x & 31;
  if (gw >= RR) return;
  const float* q = g_q + gw * DD;
  float p[NH];
  #pragma unroll
  for (int n=0;n<NH;n++) p[n] = (lane == 0) ? hyp[DD*NH + n] : 0.f;  // bias row
  #pragma unroll
  for (int i=0;i<4;i++) {
    int d = lane + i*32;
    float qd = q[d];
    #pragma unroll
    for (int n=0;n<NH;n++) p[n] = fmaf(qd, hyp[d*NH+n], p[n]);
  }
  #pragma unroll
  for (int n=0;n<NH;n++) p[n] = warpSum(p[n]);
  if (lane == 0) {
    int bk = 0;
    #pragma unroll
    for (int n=0;n<NH;n++) if (p[n] >= 0.f) bk |= (1<<n);
    g_bucket[gw] = bk;
  }
}

// Direct per-(bucket,batch) v sum + count — no zeroing, no atomics.
__global__ void k_bsum() {
  int i = blockIdx.x;   // bucket
  int b = blockIdx.y;   // batch
  int d = threadIdx.x;  // 128
  __shared__ int sb[SS];
  for (int t = d; t < SS; t += DD) sb[t] = g_bucket[b*SS + t];
  __syncthreads();
  float acc = 0.f; int cnt = 0;
  const float* vbase = g_v + (long long)b*SS*DD + d;
  for (int s = 0; s < SS; s++) {
    if (sb[s] == i) { acc += vbase[s*DD]; cnt++; }
  }
  g_vb[(b*NB+i)*DD + d] = acc;
  if (d == 0) g_cnt[b*NB + i] = cnt;
}

__global__ void k_vtot() {
  int b = blockIdx.x, d = threadIdx.x;
  float s = 0.f;
  #pragma unroll
  for (int i=0;i<NB;i++) s += g_vb[(b*NB+i)*DD + d];
  g_vtot[b*DD + d] = s;
}

// Row pass over G: max -> E=exp(scale*G - M) -> segmented sums -> Z_i, A
// -> overwrite row in place with combined weights Wc[s,t] = E*(A - invZ[bt])
__global__ void k_rowpass() {
  int r = blockIdx.x;
  int b = r >> 9;
  int sl = r & 511;
  float* Erow = g_E + (long long)r * SS;
  __shared__ float sG[SS];
  __shared__ int   sBk[SS];
  __shared__ float sEsum[NB];
  __shared__ float sInvZ[NB];
  __shared__ float sred[8];
  __shared__ float sM, sEtot, sA;
  int tid = threadIdx.x;
  int lane = tid & 31, wid = tid >> 5;
  const int* bkb = g_bucket + b*SS;
  if (tid < 128) {
    ((float4*)sG)[tid] = ((const float4*)Erow)[tid];
    ((int4*)sBk)[tid]  = ((const int4*)bkb)[tid];
  }
  if (tid < NB) sEsum[tid] = 0.f;
  __syncthreads();
  const float scale = 0.088388347648318447f; // 1/sqrt(128)
  float m = -1e30f;
  for (int t = tid; t < SS; t += 256) m = fmaxf(m, sG[t]);
  m = warpMax(m);
  if (!lane) sred[wid] = m;
  __syncthreads();
  if (tid == 0) {
    float mm = sred[0];
    #pragma unroll
    for (int i=1;i<8;i++) mm = fmaxf(mm, sred[i]);
    sM = mm;
  }
  __syncthreads();
  float M = sM * scale;
  float etot = 0.f;
  for (int t = tid; t < SS; t += 256) {
    float e = __expf(fmaf(scale, sG[t], -M));
    sG[t] = e;
    etot += e;
    atomicAdd(&sEsum[sBk[t]], e);
  }
  etot = warpSum(etot);
  if (!lane) sred[wid] = etot;
  __syncthreads();
  if (tid == 0) {
    float s = 0.f;
    #pragma unroll
    for (int i=0;i<8;i++) s += sred[i];
    sEtot = s;
  }
  __syncthreads();
  int bs = sBk[sl];
  float u = __expf(-M);
  if (tid < NB) {
    float Z = sEtot - sEsum[tid] + (float)g_cnt[b*NB+tid] * u;
    sInvZ[tid] = 1.f / Z;
  }
  __syncthreads();
  if (tid < 32) {
    float av = (tid == bs) ? 0.f : sInvZ[tid];
    av = warpSum(av);
    if (tid == 0) sA = av;
  }
  __syncthreads();
  float A = sA;
  if (tid < 128) {
    float4 o;
    float* og = &sG[tid<<2];
    int*   ob = &sBk[tid<<2];
    o.x = og[0] * (A - ((ob[0] != bs) ? sInvZ[ob[0]] : 0.f));
    o.y = og[1] * (A - ((ob[1] != bs) ? sInvZ[ob[1]] : 0.f));
    o.z = og[2] * (A - ((ob[2] != bs) ? sInvZ[ob[2]] : 0.f));
    o.w = og[3] * (A - ((ob[3] != bs) ? sInvZ[ob[3]] : 0.f));
    ((float4*)Erow)[tid] = o;
  }
}

// attention output = sum of 4 slices + (1/512)*(Vsum - V_{bucket(s)}), then LN -> g_x
__global__ void k_attn_ln(const float* __restrict__ gam, const float* __restrict__ bet) {
  int r = blockIdx.x, d = threadIdx.x;
  int b = r >> 9;
  int bs = g_bucket[r];
  float val = g_acc[r*DD+d] + g_acc[RR*DD + r*DD+d]
            + g_acc[2*RR*DD + r*DD+d] + g_acc[3*RR*DD + r*DD+d]
            + (g_vtot[b*DD+d] - g_vb[(b*NB+bs)*DD + d]) * (1.f/512.f);
  __shared__ float s1[4], s2[4];
  float su = warpSum(val), sq = warpSum(val*val);
  int lane = d & 31, wid = d >> 5;
  if (!lane) { s1[wid]=su; s2[wid]=sq; }
  __syncthreads();
  float tsum = s1[0]+s1[1]+s1[2]+s1[3];
  float tsq  = s2[0]+s2[1]+s2[2]+s2[3];
  float mu = tsum * (1.f/128.f);
  float var = tsq * (1.f/128.f) - mu*mu;
  g_x[r*DD+d] = (val-mu)*rsqrtf(var+1e-5f)*gam[d] + bet[d];
}

// x = LayerNorm(ffn slices + x)
__global__ void k_res_ln(const float* __restrict__ gam, const float* __restrict__ bet) {
  int r = blockIdx.x, d = threadIdx.x;
  float val = g_acc[r*DD+d] + g_acc[RR*DD + r*DD+d]
            + g_acc[2*RR*DD + r*DD+d] + g_acc[3*RR*DD + r*DD+d]
            + g_x[r*DD+d];
  __shared__ float s1[4], s2[4];
  float su = warpSum(val), sq = warpSum(val*val);
  int lane = d & 31, wid = d >> 5;
  if (!lane) { s1[wid]=su; s2[wid]=sq; }
  __syncthreads();
  float tsum = s1[0]+s1[1]+s1[2]+s1[3];
  float tsq  = s2[0]+s2[1]+s2[2]+s2[3];
  float mu = tsum * (1.f/128.f);
  float var = tsq * (1.f/128.f) - mu*mu;
  g_x[r*DD+d] = (val-mu)*rsqrtf(var+1e-5f)*gam[d] + bet[d];
}

// partial out: block (chunk c, batch b) reduces 8192 elements of x[b] @ Wm
__global__ void k_out1(const float* __restrict__ Wm) {
  int c = blockIdx.x, b = blockIdx.y;
  int tid = threadIdx.x;
  float acc[OO] = {};
  const float* xr = g_x + (long long)b*SS*DD;
  int base = c * 8192;
  for (int j = base + tid; j < base + 8192; j += 256) {
    float xv = xr[j];
    const float* w = Wm + (long long)j*OO;
    #pragma unroll
    for (int o=0;o<OO;o++) acc[o] = fmaf(xv, w[o], acc[o]);
  }
  __shared__ float sred[256];
  for (int o=0;o<OO;o++) {
    sred[tid] = acc[o];
    __syncthreads();
    for (int st=128; st; st>>=1) {
      if (tid < st) sred[tid] += sred[tid+st];
      __syncthreads();
    }
    if (tid == 0) g_part[(b*8+c)*OO+o] = sred[0];
    __syncthreads();
  }
}

__global__ void k_out2(const float* __restrict__ bm, float* __restrict__ out) {
  int tid = threadIdx.x;
  if (tid < BB*OO) {
    int b = tid / OO, o = tid % OO;
    float s = bm[o];
    #pragma unroll
    for (int c=0;c<8;c++) s += g_part[(b*8+c)*OO+o];
    out[b*OO+o] = s;
  }
}

extern "C" void kernel_launch(void* const* d_in, const int* in_sizes, int n_in,
                              void* d_out, int out_size) {
  const int*   idx = (const int*)  d_in[0];
  const float* emb = (const float*)d_in[1];
  const float* pe  = (const float*)d_in[2];
  const float* hyp = (const float*)d_in[3];
  const float* Wq  = (const float*)d_in[4];
  const float* bq  = (const float*)d_in[5];
  const float* Wv  = (const float*)d_in[6];
  const float* bv  = (const float*)d_in[7];
  const float* lng = (const float*)d_in[8];
  const float* lnb = (const float*)d_in[9];
  const float* W1  = (const float*)d_in[10];
  const float* b1  = (const float*)d_in[11];
  const float* W2  = (const float*)d_in[12];
  const float* b2  = (const float*)d_in[13];
  const float* Wm  = (const float*)d_in[14];
  const float* bm  = (const float*)d_in[15];
  float* out = (float*)d_out;

  float *px,*pq,*pv,*pE,*ph,*pacc,*pWqv,*pbqv;
  cudaGetSymbolAddress((void**)&px,   g_x);
  cudaGetSymbolAddress((void**)&pq,   g_q);
  cudaGetSymbolAddress((void**)&pv,   g_v);
  cudaGetSymbolAddress((void**)&pE,   g_E);
  cudaGetSymbolAddress((void**)&ph,   g_h);
  cudaGetSymbolAddress((void**)&pacc, g_acc);
  cudaGetSymbolAddress((void**)&pWqv, g_Wqv);
  cudaGetSymbolAddress((void**)&pbqv, g_bqv);

  k_prep<<<128,256>>>(Wq, bq, Wv, bv);
  k_embed<<<RR, DD>>>(idx, emb, pe);
  for (int e = 0; e < 2; e++) {
    // fused q|v projection (exact fp32): [4096,128]@[128,256] -> g_q/g_v
    k_qv<<<dim3(4,32,1),256>>>(px, pWqv, pbqv);
    // buckets + per-bucket v sums (atomic-free)
    k_bucket<<<512,256>>>(hyp);
    k_bsum<<<dim3(NB,BB),DD>>>();
    k_vtot<<<BB,DD>>>();
    // G = q @ q^T (batched, tf32 tensor cores)
    k_mma<true,false,false,1><<<dim3(4,4,BB),256>>>(
        pq, pq, nullptr, pE, SS, DD, DD,
        (long long)SS*DD, (long long)SS*DD, (long long)SS*SS, 0);
    // combined per-row softmax weights (in place)
    k_rowpass<<<RR,256>>>();
    // acc = Wc @ v (tf32, split-K=4)
    k_mma<false,false,false,4><<<dim3(1,4,BB*4),256>>>(
        pE, pv, nullptr, pacc, DD, SS, DD,
        (long long)SS*SS, (long long)SS*DD, (long long)SS*DD, (long long)RR*DD);
    // + uniform bucket term, then LN
    k_attn_ln<<<RR,DD>>>(lng, lnb);
    // FFN (tf32): h = relu(x@W1+b1); acc = h@W2 (+b2 on slice0, split-K=4)
    k_mma<false,true ,true ,1><<<dim3(4,32,1),256>>>(
        px, W1, b1, ph, HH, DD, HH, 0,0,0,0);
    k_mma<false,false,true ,4><<<dim3(1,32,4),256>>>(
        ph, W2, b2, pacc, DD, HH, DD, 0,0,0, (long long)RR*DD);
    k_res_ln<<<RR,DD>>>(lng, lnb);
  }
  k_out1<<<dim3(8,BB),256>>>(Wm);
  k_out2<<<1,64>>>(bm, out);
}